// round 8
// baseline (speedup 1.0000x reference)
#include <cuda_runtime.h>
#include <cuda_bf16.h>

// NSLoss fused single-kernel, warp-per-gather mapping.
// loss = -(1/n) * sum_i [ log_sigmoid(<emb_i, W[label_i]>)
//                         + sum_k log_sigmoid(-<emb_i, W[negs_ik]>) ]
// Inputs: y_hat f32[N] (unused), emb f32[N,128], weights f32[1e6,128],
// label i32[N], negs i32[N,10]. Output: f32 scalar.
//
// CTA = 352 threads = 11 warps. Warp w owns sample-component k=w
// (w==0 -> label, w>=1 -> neg w-1) for S=4 consecutive samples.
// Each warp issues only 4 weight gathers (MLP_p1 ~ 4-8, vs 12 before)
// to avoid the cross-CTA L1tex-queue spread from front-batched bursts.
// emb rows are read by all 11 warps of a CTA -> 10/11 are L1 hits.
// Last arriving block finalizes and resets state (graph-replayable).

#define D 128
#define NUM_SAMPLED 10
#define NROWS (NUM_SAMPLED + 1)   // 11 warps per CTA
#define S 4                        // samples per CTA
#define THREADS (NROWS * 32)       // 352
#define NUM_NODES 1000000

__device__ double g_acc = 0.0;
__device__ unsigned int g_arrived = 0;

__device__ __forceinline__ float log_sigmoid_f(float x) {
    return fminf(x, 0.0f) - log1pf(__expf(-fabsf(x)));
}

__global__ __launch_bounds__(THREADS)
void nsloss_wpg_kernel(const float* __restrict__ emb,
                       const float* __restrict__ weights,
                       const int* __restrict__ label,
                       const int* __restrict__ negs,
                       float* __restrict__ out,
                       int n) {
    const int lane = threadIdx.x & 31;
    const int w    = threadIdx.x >> 5;          // component k = w (0..10)
    const int i0   = blockIdx.x * S;

    // ---- indices for this warp's component across S samples ----
    int idx[S];
    #pragma unroll
    for (int s = 0; s < S; ++s) {
        int i = i0 + s;
        int v = 0;
        if (i < n)
            v = (w == 0) ? label[i] : negs[i * NUM_SAMPLED + (w - 1)];
        idx[s] = min(max(v, 0), NUM_NODES - 1);
    }

    // ---- batched loads: 4 weight gathers + 4 emb rows (emb mostly L1) ----
    float4 wrow[S], erow[S];
    #pragma unroll
    for (int s = 0; s < S; ++s)
        wrow[s] = reinterpret_cast<const float4*>(weights + (size_t)idx[s] * D)[lane];
    #pragma unroll
    for (int s = 0; s < S; ++s) {
        int i = min(i0 + s, n - 1);
        erow[s] = reinterpret_cast<const float4*>(emb + (size_t)i * D)[lane];
    }

    // ---- 4 independent dots, butterfly stages interleaved (4-way ILP) ----
    float d[S];
    #pragma unroll
    for (int s = 0; s < S; ++s)
        d[s] = erow[s].x * wrow[s].x + erow[s].y * wrow[s].y
             + erow[s].z * wrow[s].z + erow[s].w * wrow[s].w;
    #pragma unroll
    for (int off = 16; off > 0; off >>= 1) {
        #pragma unroll
        for (int s = 0; s < S; ++s)
            d[s] += __shfl_xor_sync(0xffffffffu, d[s], off);
    }

    // ---- per-warp contribution (lane 0): log-sigmoid of +/- dot ----
    float contrib = 0.0f;
    if (lane == 0) {
        #pragma unroll
        for (int s = 0; s < S; ++s) {
            if (i0 + s < n) {
                float sc = (w == 0) ? d[s] : -d[s];
                contrib += log_sigmoid_f(sc);
            }
        }
    }

    // ---- block reduce + global accumulate ----
    __shared__ float warp_sums[NROWS];
    __shared__ bool is_last;
    if (lane == 0) warp_sums[w] = contrib;
    __syncthreads();

    if (threadIdx.x == 0) {
        float ssum = 0.0f;
        #pragma unroll
        for (int k = 0; k < NROWS; ++k) ssum += warp_sums[k];
        atomicAdd(&g_acc, (double)ssum);
        __threadfence();
        unsigned int prev = atomicAdd(&g_arrived, 1u);
        is_last = (prev == gridDim.x - 1);
    }
    __syncthreads();

    if (is_last && threadIdx.x == 0) {
        double total = g_acc;
        out[0] = (float)(-total / (double)n);
        g_acc = 0.0;
        g_arrived = 0u;
        __threadfence();
    }
}

extern "C" void kernel_launch(void* const* d_in, const int* in_sizes, int n_in,
                              void* d_out, int out_size) {
    const float* emb     = (const float*)d_in[1];
    const float* weights = (const float*)d_in[2];
    const int*   label   = (const int*)d_in[3];
    const int*   negs    = (const int*)d_in[4];
    float* out = (float*)d_out;

    const int n = in_sizes[0];              // N from y_hat length
    const int blocks = (n + S - 1) / S;

    nsloss_wpg_kernel<<<blocks, THREADS>>>(emb, weights, label, negs, out, n);
}

// round 12
// speedup vs baseline: 1.3714x; 1.3714x over previous
#include <cuda_runtime.h>
#include <cuda_bf16.h>

// NSLoss fused single-kernel. 256-bit gathers with L2::evict_last residency
// (sm_103 ptxas only accepts the evict hint on .v8.b32/.v4.b64 loads).
// loss = -(1/n) * sum_i [ log_sigmoid(<emb_i, W[label_i]>)
//                         + sum_k log_sigmoid(-<emb_i, W[negs_ik]>) ]
// Inputs: y_hat f32[N] (unused), emb f32[N,128], weights f32[1e6,128],
// label i32[N], negs i32[N,10]. Output: f32 scalar.
//
// Warp-per-sample. Each lane loads 8 floats (32B); one warp load covers TWO
// weight rows (lanes 0-15 -> slot 2p, lanes 16-31 -> slot 2p+1). 12 slots =
// label + 10 negs + slot11 aliased to label (broadcast, no extra traffic).
// 6 paired gathers + emb all in flight; 4-stage half-warp butterfly.

#define D 128
#define NUM_SAMPLED 10
#define NPAIRS 6                   // 12 slots / 2
#define THREADS 256
#define WARPS_PER_BLOCK (THREADS / 32)
#define NUM_NODES 1000000

__device__ double g_acc = 0.0;
__device__ unsigned int g_arrived = 0;

__device__ __forceinline__ float log_sigmoid_f(float x) {
    return fminf(x, 0.0f) - log1pf(__expf(-fabsf(x)));
}

// 32-byte load (8 floats) with L2 evict_last residency hint.
__device__ __forceinline__ void ld_el_8f(const float* p, float* v) {
    unsigned long long a, b, c, d;
    asm volatile("ld.global.nc.L2::evict_last.v4.b64 {%0,%1,%2,%3}, [%4];"
                 : "=l"(a), "=l"(b), "=l"(c), "=l"(d) : "l"(p));
    v[0] = __uint_as_float((unsigned)a); v[1] = __uint_as_float((unsigned)(a >> 32));
    v[2] = __uint_as_float((unsigned)b); v[3] = __uint_as_float((unsigned)(b >> 32));
    v[4] = __uint_as_float((unsigned)c); v[5] = __uint_as_float((unsigned)(c >> 32));
    v[6] = __uint_as_float((unsigned)d); v[7] = __uint_as_float((unsigned)(d >> 32));
}

__global__ __launch_bounds__(THREADS)
void nsloss_fused_kernel(const float* __restrict__ emb,
                         const float* __restrict__ weights,
                         const int* __restrict__ label,
                         const int* __restrict__ negs,
                         float* __restrict__ out,
                         int n) {
    const int lane = threadIdx.x & 31;
    const int half = lane >> 4;             // 0: even slots, 1: odd slots
    const int col8 = (lane & 15) * 8;       // this lane's 8-float column chunk
    const int warp_in_blk = threadIdx.x >> 5;
    const int i = blockIdx.x * WARPS_PER_BLOCK + warp_in_blk;

    float warp_partial = 0.0f;

    if (i < n) {
        // Slot indices: lane 0 -> label, lanes 1..10 -> negs. Broadcast by shuffle.
        int my_idx = 0;
        if (lane == 0)                my_idx = label[i];
        else if (lane <= NUM_SAMPLED) my_idx = negs[i * NUM_SAMPLED + (lane - 1)];
        my_idx = min(max(my_idx, 0), NUM_NODES - 1);

        // emb chunk (lanes l and l+16 read the same 32B -> broadcast).
        float e8[8];
        ld_el_8f(emb + (size_t)i * D + col8, e8);

        // All 6 paired weight gathers in flight. Pair p: half 0 reads slot 2p,
        // half 1 reads slot 2p+1; slot 11 aliases slot 0 (label, discarded).
        float w8[NPAIRS][8];
        #pragma unroll
        for (int p = 0; p < NPAIRS; ++p) {
            int slot = 2 * p + half;
            if (slot == 11) slot = 0;
            int row = __shfl_sync(0xffffffffu, my_idx, slot);
            ld_el_8f(weights + (size_t)row * D + col8, w8[p]);
        }

        // 6 independent 8-wide partial dots.
        float dp[NPAIRS];
        #pragma unroll
        for (int p = 0; p < NPAIRS; ++p) {
            float s = 0.0f;
            #pragma unroll
            for (int j = 0; j < 8; ++j) s = fmaf(e8[j], w8[p][j], s);
            dp[p] = s;
        }

        // Butterfly within each 16-lane half (4 stages, 6-way ILP).
        #pragma unroll
        for (int off = 8; off > 0; off >>= 1) {
            #pragma unroll
            for (int p = 0; p < NPAIRS; ++p)
                dp[p] += __shfl_xor_sync(0xffffffffu, dp[p], off);
        }
        // Now lane in half h holds full dot of slot 2p+h in dp[p].

        // Lane 0: even slots (0=label positive, 2,4,6,8,10 negatives).
        // Lane 16: odd slots (1,3,5,7,9 negatives; pair 5 = slot11 discard).
        float contrib = 0.0f;
        if (lane == 0) {
            contrib = log_sigmoid_f(dp[0]);               // label: +dot
            #pragma unroll
            for (int p = 1; p < NPAIRS; ++p)
                contrib += log_sigmoid_f(-dp[p]);
        } else if (lane == 16) {
            #pragma unroll
            for (int p = 0; p < NPAIRS - 1; ++p)
                contrib += log_sigmoid_f(-dp[p]);
        }
        contrib += __shfl_xor_sync(0xffffffffu, contrib, 16);
        warp_partial = contrib;   // lanes 0 and 16 now both hold the total
    }

    // Block reduce + global accumulate.
    __shared__ float warp_sums[WARPS_PER_BLOCK];
    __shared__ bool is_last;
    if (lane == 0) warp_sums[warp_in_blk] = warp_partial;
    __syncthreads();

    if (threadIdx.x == 0) {
        float s = 0.0f;
        #pragma unroll
        for (int wi = 0; wi < WARPS_PER_BLOCK; ++wi) s += warp_sums[wi];
        atomicAdd(&g_acc, (double)s);
        __threadfence();
        unsigned int prev = atomicAdd(&g_arrived, 1u);
        is_last = (prev == gridDim.x - 1);
    }
    __syncthreads();

    // Last block finalizes: write output, reset state for next graph replay.
    if (is_last && threadIdx.x == 0) {
        double total = g_acc;
        out[0] = (float)(-total / (double)n);
        g_acc = 0.0;
        g_arrived = 0u;
        __threadfence();
    }
}

extern "C" void kernel_launch(void* const* d_in, const int* in_sizes, int n_in,
                              void* d_out, int out_size) {
    const float* emb     = (const float*)d_in[1];
    const float* weights = (const float*)d_in[2];
    const int*   label   = (const int*)d_in[3];
    const int*   negs    = (const int*)d_in[4];
    float* out = (float*)d_out;

    const int n = in_sizes[0];              // N from y_hat length
    const int blocks = (n + WARPS_PER_BLOCK - 1) / WARPS_PER_BLOCK;

    nsloss_fused_kernel<<<blocks, THREADS>>>(emb, weights, label, negs, out, n);
}

// round 15
// speedup vs baseline: 1.7306x; 1.2619x over previous
#include <cuda_runtime.h>
#include <cuda_bf16.h>

// NSLoss persistent grid-stride kernel.
// loss = -(1/n) * sum_i [ log_sigmoid(<emb_i, W[label_i]>)
//                         + sum_k log_sigmoid(-<emb_i, W[negs_ik]>) ]
// Inputs: y_hat f32[N] (unused), emb f32[N,128], weights f32[1e6,128],
// label i32[N], negs i32[N,10]. Output: f32 scalar.
//
// Evidence (R5/R6/R11): kernel is pinned at the random-512B-gather DRAM floor
// (~3.5TB/s) regardless of occupancy/MLP shape. This variant removes the
// remaining non-floor overhead: persistent grid (4 CTAs/SM x 148 SMs) so the
// DRAM queue never drains at wave boundaries, per-warp accumulation across
// iterations, one block reduction + one global atomic per CTA (592 total).

#define D 128
#define NUM_SAMPLED 10
#define NROWS (NUM_SAMPLED + 1)
#define THREADS 256
#define WARPS_PER_BLOCK (THREADS / 32)
#define CTAS_PER_SM 4
#define NUM_SMS 148
#define GRID_BLOCKS (NUM_SMS * CTAS_PER_SM)   /* 592 */
#define NUM_NODES 1000000

__device__ double g_acc = 0.0;
__device__ unsigned int g_arrived = 0;

__device__ __forceinline__ float log_sigmoid_f(float x) {
    return fminf(x, 0.0f) - log1pf(__expf(-fabsf(x)));
}

__global__ __launch_bounds__(THREADS, CTAS_PER_SM)
void nsloss_persist_kernel(const float* __restrict__ emb,
                           const float* __restrict__ weights,
                           const int* __restrict__ label,
                           const int* __restrict__ negs,
                           float* __restrict__ out,
                           int n) {
    const int lane = threadIdx.x & 31;
    const int warp_in_blk = threadIdx.x >> 5;
    const int warp_gid = (blockIdx.x * THREADS + threadIdx.x) >> 5;
    const int warp_stride = (GRID_BLOCKS * THREADS) >> 5;   // 4736 warps

    float acc_total = 0.0f;   // lane-uniform accumulation across iterations

    for (int i = warp_gid; i < n; i += warp_stride) {
        // ---- indices: lane 0 -> label, lanes 1..10 -> negs ----
        int my_idx = 0;
        if (lane == 0)                my_idx = label[i];
        else if (lane <= NUM_SAMPLED) my_idx = negs[i * NUM_SAMPLED + (lane - 1)];
        my_idx = min(max(my_idx, 0), NUM_NODES - 1);

        // ---- all loads batched: emb (coalesced 512B) + 11 gathers in flight ----
        const float4 e = reinterpret_cast<const float4*>(emb + (size_t)i * D)[lane];
        float4 w[NROWS];
        #pragma unroll
        for (int k = 0; k < NROWS; ++k) {
            int row = __shfl_sync(0xffffffffu, my_idx, k);
            w[k] = reinterpret_cast<const float4*>(weights + (size_t)row * D)[lane];
        }

        // ---- 11 independent partial dots ----
        float d[NROWS];
        #pragma unroll
        for (int k = 0; k < NROWS; ++k)
            d[k] = e.x * w[k].x + e.y * w[k].y + e.z * w[k].z + e.w * w[k].w;

        // ---- butterfly interleaved across all 11 dots (ILP hides SHFL lat) ----
        #pragma unroll
        for (int off = 16; off > 0; off >>= 1) {
            #pragma unroll
            for (int k = 0; k < NROWS; ++k)
                d[k] += __shfl_xor_sync(0xffffffffu, d[k], off);
        }

        // ---- lane k evaluates sample-component k (1 log-sigmoid per lane) ----
        float mydot = 0.0f;
        #pragma unroll
        for (int k = 0; k < NROWS; ++k)
            if (lane == k) mydot = d[k];
        float contrib = 0.0f;
        if (lane < NROWS) {
            float s = (lane == 0) ? mydot : -mydot;
            contrib = log_sigmoid_f(s);
        }
        #pragma unroll
        for (int off = 16; off > 0; off >>= 1)
            contrib += __shfl_xor_sync(0xffffffffu, contrib, off);
        acc_total += contrib;   // lane-uniform
    }

    // ---- one block reduction + one global atomic per CTA ----
    __shared__ float warp_sums[WARPS_PER_BLOCK];
    __shared__ bool is_last;
    if (lane == 0) warp_sums[warp_in_blk] = acc_total;
    __syncthreads();

    if (threadIdx.x == 0) {
        float s = 0.0f;
        #pragma unroll
        for (int wi = 0; wi < WARPS_PER_BLOCK; ++wi) s += warp_sums[wi];
        atomicAdd(&g_acc, (double)s);
        __threadfence();
        unsigned int prev = atomicAdd(&g_arrived, 1u);
        is_last = (prev == gridDim.x - 1);
    }
    __syncthreads();

    // Last block finalizes: write output, reset state for next graph replay.
    if (is_last && threadIdx.x == 0) {
        double total = g_acc;
        out[0] = (float)(-total / (double)n);
        g_acc = 0.0;
        g_arrived = 0u;
        __threadfence();
    }
}

extern "C" void kernel_launch(void* const* d_in, const int* in_sizes, int n_in,
                              void* d_out, int out_size) {
    const float* emb     = (const float*)d_in[1];
    const float* weights = (const float*)d_in[2];
    const int*   label   = (const int*)d_in[3];
    const int*   negs    = (const int*)d_in[4];
    float* out = (float*)d_out;

    const int n = in_sizes[0];              // N from y_hat length

    nsloss_persist_kernel<<<GRID_BLOCKS, THREADS>>>(emb, weights, label, negs, out, n);
}